// round 1
// baseline (speedup 1.0000x reference)
#include <cuda_runtime.h>
#include <cuda_bf16.h>
#include <math.h>

#define N_NODES 50000
#define N_EDGES 800000
#define N_PAIRS 100000
#define IN_CH 128
#define HID 256
#define EMB 32
#define CAT_EMB 8
#define MAX_TOK 20
#define F0 160   // IN_CH + EMB
#define F1 256   // HID

// ---------------- scratch (static __device__ arrays; no allocation) ----------------
__device__ float g_h0[N_NODES * F0];    // concat(x, gwas_feat)
__device__ float g_agg[N_NODES * F1];   // aggregation scratch (sized for max F)
__device__ float g_h1[N_NODES * F1];    // layer-0 output
__device__ float g_z[N_NODES * F1];     // layer-1 output
__device__ int   g_cnt[N_NODES];
__device__ int   g_off[N_NODES + 1];
__device__ int   g_cur[N_NODES];
__device__ int   g_csr[N_EDGES];
__device__ float g_invdeg[N_NODES];

// ---------------- GWAS encoder + concat into h0 ----------------
// One warp per node. Linear trick: out = ((sum_t w_t * in_t) @ W + (sum w)*b) / max(sum w, 1e-8)
__global__ void gwas_kernel(const float* __restrict__ x,
                            const int* __restrict__ tok,
                            const float* __restrict__ scores,
                            const int* __restrict__ cat,
                            const float* __restrict__ trait_embed,
                            const float* __restrict__ cat_embed,
                            const float* __restrict__ proj_W,
                            const float* __restrict__ proj_b) {
    int warp_in_block = threadIdx.x >> 5;
    int lane = threadIdx.x & 31;
    int n = blockIdx.x * (blockDim.x >> 5) + warp_in_block;
    if (n >= N_NODES) return;

    __shared__ float sh_acc[8][41];   // 8 warps per block
    float acc_trait = 0.f;            // lane -> trait channel
    float acc_cat   = 0.f;            // lanes 0..7 -> cat channels
    float acc_s     = 0.f;
    float wsum      = 0.f;

    const int*   tk = tok    + (long long)n * MAX_TOK;
    const float* sc = scores + (long long)n * MAX_TOK;
    const int*   ct = cat    + (long long)n * MAX_TOK;

    for (int t = 0; t < MAX_TOK; ++t) {
        int   tid = tk[t];           // broadcast loads (same addr all lanes)
        float s   = sc[t];
        int   cid = ct[t];
        float w   = (tid != 0) ? s : 0.f;
        wsum += w;
        acc_trait += w * trait_embed[tid * EMB + lane];
        if (lane < CAT_EMB) acc_cat += w * cat_embed[cid * CAT_EMB + lane];
        acc_s += w * s;
    }
    sh_acc[warp_in_block][lane] = acc_trait;
    if (lane < CAT_EMB) sh_acc[warp_in_block][EMB + lane] = acc_cat;
    if (lane == 0)      sh_acc[warp_in_block][EMB + CAT_EMB] = acc_s;
    __syncwarp();

    float denom = fmaxf(wsum, 1e-8f);
    float inv   = 1.f / denom;

    // matvec: out[lane] = (acc41 @ W)[lane] + wsum * b[lane]
    float o = wsum * proj_b[lane];
    const float* shv = sh_acc[warp_in_block];
#pragma unroll
    for (int k = 0; k < 41; ++k)
        o += shv[k] * proj_W[k * EMB + lane];

    float* hrow = g_h0 + (long long)n * F0;
    hrow[IN_CH + lane] = o * inv;
    // copy x part (128 floats, 4 per lane)
    const float* xrow = x + (long long)n * IN_CH;
#pragma unroll
    for (int i = 0; i < 4; ++i)
        hrow[lane + i * 32] = xrow[lane + i * 32];
}

// ---------------- CSR build ----------------
__global__ void zero_cnt_kernel() {
    int i = blockIdx.x * blockDim.x + threadIdx.x;
    if (i < N_NODES) g_cnt[i] = 0;
}

__global__ void count_kernel(const int* __restrict__ e_dst) {
    int e = blockIdx.x * blockDim.x + threadIdx.x;
    if (e < N_EDGES) atomicAdd(&g_cnt[e_dst[e]], 1);
}

__global__ void scan_kernel() {
    __shared__ int sh[1024];
    __shared__ int carry_s;
    int tid = threadIdx.x;
    if (tid == 0) carry_s = 0;
    __syncthreads();
    for (int base = 0; base < N_NODES; base += 1024) {
        int i = base + tid;
        int v = (i < N_NODES) ? g_cnt[i] : 0;
        sh[tid] = v;
        __syncthreads();
        for (int off = 1; off < 1024; off <<= 1) {
            int t = (tid >= off) ? sh[tid - off] : 0;
            __syncthreads();
            sh[tid] += t;
            __syncthreads();
        }
        int carry = carry_s;
        if (i < N_NODES) {
            int o = carry + sh[tid] - v;
            g_off[i] = o;
            g_cur[i] = o;
            g_invdeg[i] = 1.0f / fmaxf((float)v, 1.0f);
        }
        __syncthreads();
        if (tid == 1023) carry_s = carry + sh[1023];
        __syncthreads();
    }
    if (tid == 0) g_off[N_NODES] = carry_s;
}

__global__ void fill_kernel(const int* __restrict__ e_src, const int* __restrict__ e_dst) {
    int e = blockIdx.x * blockDim.x + threadIdx.x;
    if (e < N_EDGES) {
        int d = e_dst[e];
        int pos = atomicAdd(&g_cur[d], 1);
        g_csr[pos] = e_src[e];
    }
}

// ---------------- mean aggregation (gather via CSR) ----------------
// block = F threads, one node per block
__global__ void aggregate_kernel(int layer) {
    const float* feat = layer ? g_h1 : g_h0;
    int F = layer ? F1 : F0;
    int n = blockIdx.x;
    int c = threadIdx.x;
    int s = g_off[n], e = g_off[n + 1];
    float acc = 0.f;
    for (int j = s; j < e; ++j) {
        int srcn = g_csr[j];
        acc += feat[(long long)srcn * F + c];
    }
    g_agg[(long long)n * F + c] = acc * g_invdeg[n];
}

// ---------------- fused dual GEMM: C = relu(agg@Wl + x@Wr + b) ----------------
#define BM 64
#define BN 64
#define BK 16
__global__ void gemm_fused_kernel(const float* __restrict__ Wl,
                                  const float* __restrict__ Wr,
                                  const float* __restrict__ bias,
                                  int layer) {
    const float* Xin = layer ? g_h1 : g_h0;
    float* C = layer ? g_z : g_h1;
    int F = layer ? F1 : F0;

    __shared__ float As[BK][BM + 4];
    __shared__ float Bs[BK][BN + 4];

    int tx = threadIdx.x;                 // 0..255
    int row0 = blockIdx.x * BM;
    int col0 = blockIdx.y * BN;
    int tm = tx >> 4;                     // 0..15
    int tn = tx & 15;                     // 0..15

    float acc[4][4];
#pragma unroll
    for (int i = 0; i < 4; ++i)
#pragma unroll
        for (int j = 0; j < 4; ++j) acc[i][j] = 0.f;

    for (int phase = 0; phase < 2; ++phase) {
        const float* Ap = phase ? Xin : g_agg;
        const float* Wp = phase ? Wr : Wl;
        for (int k0 = 0; k0 < F; k0 += BK) {
            // load A tile: 64 rows x 16 k
#pragma unroll
            for (int i = tx; i < BM * BK; i += 256) {
                int m = i >> 4, k = i & 15;
                int gm = row0 + m;
                As[k][m] = (gm < N_NODES) ? Ap[(long long)gm * F + k0 + k] : 0.f;
            }
            // load W tile: 16 k x 64 n
#pragma unroll
            for (int i = tx; i < BK * BN; i += 256) {
                int k = i >> 6, nn = i & 63;
                Bs[k][nn] = Wp[(long long)(k0 + k) * HID + col0 + nn];
            }
            __syncthreads();
#pragma unroll
            for (int k = 0; k < BK; ++k) {
                float a[4], b[4];
#pragma unroll
                for (int i = 0; i < 4; ++i) a[i] = As[k][tm * 4 + i];
#pragma unroll
                for (int j = 0; j < 4; ++j) b[j] = Bs[k][tn * 4 + j];
#pragma unroll
                for (int i = 0; i < 4; ++i)
#pragma unroll
                    for (int j = 0; j < 4; ++j) acc[i][j] += a[i] * b[j];
            }
            __syncthreads();
        }
    }
#pragma unroll
    for (int i = 0; i < 4; ++i) {
        int gm = row0 + tm * 4 + i;
        if (gm < N_NODES) {
#pragma unroll
            for (int j = 0; j < 4; ++j) {
                int gn = col0 + tn * 4 + j;
                float v = acc[i][j] + bias[gn];
                C[(long long)gm * HID + gn] = fmaxf(v, 0.f);
            }
        }
    }
}

// ---------------- pair scoring: sigmoid(dot(z[src], z[dst])) ----------------
__global__ void pair_kernel(const int* __restrict__ src,
                            const int* __restrict__ dst,
                            float* __restrict__ out) {
    int gw = (blockIdx.x * blockDim.x + threadIdx.x) >> 5;
    int lane = threadIdx.x & 31;
    if (gw >= N_PAIRS) return;
    int a = src[gw], b = dst[gw];
    const float4* za = (const float4*)(g_z + (long long)a * HID);
    const float4* zb = (const float4*)(g_z + (long long)b * HID);
    float acc = 0.f;
#pragma unroll
    for (int i = 0; i < 2; ++i) {
        float4 va = za[lane + i * 32];
        float4 vb = zb[lane + i * 32];
        acc += va.x * vb.x + va.y * vb.y + va.z * vb.z + va.w * vb.w;
    }
#pragma unroll
    for (int o = 16; o; o >>= 1) acc += __shfl_xor_sync(0xFFFFFFFFu, acc, o);
    if (lane == 0) out[gw] = 1.f / (1.f + expf(-acc));
}

// ---------------- launch ----------------
extern "C" void kernel_launch(void* const* d_in, const int* in_sizes, int n_in,
                              void* d_out, int out_size) {
    const float* x           = (const float*)d_in[0];
    const int*   tok_ids     = (const int*)  d_in[1];
    const float* scores      = (const float*)d_in[2];
    const int*   cat_ids     = (const int*)  d_in[3];
    const int*   edge_index  = (const int*)  d_in[4];
    const int*   src         = (const int*)  d_in[5];
    const int*   dst         = (const int*)  d_in[6];
    const float* trait_embed = (const float*)d_in[7];
    const float* cat_embed   = (const float*)d_in[8];
    const float* proj_W      = (const float*)d_in[9];
    const float* proj_b      = (const float*)d_in[10];
    const float* W_l0        = (const float*)d_in[11];
    const float* b_l0        = (const float*)d_in[12];
    const float* W_r0        = (const float*)d_in[13];
    const float* W_l1        = (const float*)d_in[14];
    const float* b_l1        = (const float*)d_in[15];
    const float* W_r1        = (const float*)d_in[16];
    float* out = (float*)d_out;

    const int* e_src = edge_index;
    const int* e_dst = edge_index + N_EDGES;

    // GWAS encode + concat -> g_h0
    gwas_kernel<<<(N_NODES + 7) / 8, 256>>>(x, tok_ids, scores, cat_ids,
                                            trait_embed, cat_embed, proj_W, proj_b);

    // CSR build
    zero_cnt_kernel<<<(N_NODES + 255) / 256, 256>>>();
    count_kernel<<<(N_EDGES + 255) / 256, 256>>>(e_dst);
    scan_kernel<<<1, 1024>>>();
    fill_kernel<<<(N_EDGES + 255) / 256, 256>>>(e_src, e_dst);

    // Layer 0
    aggregate_kernel<<<N_NODES, F0>>>(0);
    {
        dim3 grid((N_NODES + BM - 1) / BM, HID / BN);
        gemm_fused_kernel<<<grid, 256>>>(W_l0, W_r0, b_l0, 0);
    }

    // Layer 1
    aggregate_kernel<<<N_NODES, F1>>>(1);
    {
        dim3 grid((N_NODES + BM - 1) / BM, HID / BN);
        gemm_fused_kernel<<<grid, 256>>>(W_l1, W_r1, b_l1, 1);
    }

    // Pair scoring
    pair_kernel<<<(N_PAIRS * 32 + 255) / 256, 256>>>(src, dst, out);
}

// round 2
// speedup vs baseline: 2.1007x; 2.1007x over previous
#include <cuda_runtime.h>
#include <cuda_bf16.h>
#include <math.h>

#define N_NODES 50000
#define N_EDGES 800000
#define N_PAIRS 100000
#define IN_CH 128
#define HID 256
#define EMB 32
#define CAT_EMB 8
#define MAX_TOK 20
#define F0 160   // IN_CH + EMB
#define F1 256   // HID

// ---------------- scratch (static __device__ arrays; no allocation) ----------------
__device__ float g_h0[N_NODES * F0];    // concat(x, gwas_feat)
__device__ float g_agg[N_NODES * F1];   // aggregation scratch (sized for max F)
__device__ float g_h1[N_NODES * F1];    // layer-0 output
__device__ float g_z[N_NODES * F1];     // layer-1 output
__device__ int   g_cnt[N_NODES];
__device__ int   g_off[N_NODES + 1];
__device__ int   g_cur[N_NODES];
__device__ int   g_csr[N_EDGES];
__device__ float g_invdeg[N_NODES];

#define SCAN_BLK 256
#define SCAN_GRID ((N_NODES + SCAN_BLK - 1) / SCAN_BLK)   // 196
__device__ int g_bsum[SCAN_GRID];

// ---------------- f32x2 packed-FMA helpers ----------------
#define FMA2(c, a, b) \
    asm("fma.rn.f32x2 %0, %1, %2, %3;" : "=l"(c) : "l"(a), "l"(b), "l"(c))
#define PACK_DUP(out, fv) \
    asm("mov.b64 %0, {%1, %1};" : "=l"(out) : "r"(__float_as_uint(fv)))
#define UNPACK2(lo, hi, in) \
    asm("mov.b64 {%0, %1}, %2;" : "=r"(lo), "=r"(hi) : "l"(in))

// ---------------- GWAS encoder + concat into h0 ----------------
// One warp per node. Linear trick: out = ((sum_t w_t*in_t) @ W + (sum w)*b) / max(sum w,1e-8)
__global__ void gwas_kernel(const float* __restrict__ x,
                            const int* __restrict__ tok,
                            const float* __restrict__ scores,
                            const int* __restrict__ cat,
                            const float* __restrict__ trait_embed,
                            const float* __restrict__ cat_embed,
                            const float* __restrict__ proj_W,
                            const float* __restrict__ proj_b) {
    int warp_in_block = threadIdx.x >> 5;
    int lane = threadIdx.x & 31;
    int n = blockIdx.x * (blockDim.x >> 5) + warp_in_block;
    if (n >= N_NODES) return;

    __shared__ float sh_acc[8][41];
    float acc_trait = 0.f;
    float acc_cat   = 0.f;
    float acc_s     = 0.f;
    float wsum      = 0.f;

    const int*   tk = tok    + (long long)n * MAX_TOK;
    const float* sc = scores + (long long)n * MAX_TOK;
    const int*   ct = cat    + (long long)n * MAX_TOK;

    for (int t = 0; t < MAX_TOK; ++t) {
        int   tid = tk[t];
        float s   = sc[t];
        int   cid = ct[t];
        float w   = (tid != 0) ? s : 0.f;
        wsum += w;
        acc_trait += w * trait_embed[tid * EMB + lane];
        if (lane < CAT_EMB) acc_cat += w * cat_embed[cid * CAT_EMB + lane];
        acc_s += w * s;
    }
    sh_acc[warp_in_block][lane] = acc_trait;
    if (lane < CAT_EMB) sh_acc[warp_in_block][EMB + lane] = acc_cat;
    if (lane == 0)      sh_acc[warp_in_block][EMB + CAT_EMB] = acc_s;
    __syncwarp();

    float inv = 1.f / fmaxf(wsum, 1e-8f);

    float o = wsum * proj_b[lane];
    const float* shv = sh_acc[warp_in_block];
#pragma unroll
    for (int k = 0; k < 41; ++k)
        o += shv[k] * proj_W[k * EMB + lane];

    float* hrow = g_h0 + (long long)n * F0;
    hrow[IN_CH + lane] = o * inv;
    const float* xrow = x + (long long)n * IN_CH;
#pragma unroll
    for (int i = 0; i < 4; ++i)
        hrow[lane + i * 32] = xrow[lane + i * 32];
}

// ---------------- CSR build ----------------
__global__ void zero_cnt_kernel() {
    int i = blockIdx.x * blockDim.x + threadIdx.x;
    if (i < N_NODES) g_cnt[i] = 0;
}

__global__ void count_kernel(const int* __restrict__ e_dst) {
    int e = blockIdx.x * blockDim.x + threadIdx.x;
    if (e < N_EDGES) atomicAdd(&g_cnt[e_dst[e]], 1);
}

// block-local inclusive scans, write local-exclusive offsets + block sums
__global__ void scan1_kernel() {
    __shared__ int sh[SCAN_BLK];
    int tid = threadIdx.x;
    int i = blockIdx.x * SCAN_BLK + tid;
    int v = (i < N_NODES) ? g_cnt[i] : 0;
    sh[tid] = v;
    __syncthreads();
#pragma unroll
    for (int off = 1; off < SCAN_BLK; off <<= 1) {
        int t = (tid >= off) ? sh[tid - off] : 0;
        __syncthreads();
        sh[tid] += t;
        __syncthreads();
    }
    if (i < N_NODES) g_off[i] = sh[tid] - v;   // local exclusive
    if (tid == SCAN_BLK - 1) g_bsum[blockIdx.x] = sh[tid];
}

// single block: exclusive scan of the 196 block sums
__global__ void scan2_kernel() {
    __shared__ int sh[SCAN_BLK];
    int tid = threadIdx.x;
    int v = (tid < SCAN_GRID) ? g_bsum[tid] : 0;
    sh[tid] = v;
    __syncthreads();
#pragma unroll
    for (int off = 1; off < SCAN_BLK; off <<= 1) {
        int t = (tid >= off) ? sh[tid - off] : 0;
        __syncthreads();
        sh[tid] += t;
        __syncthreads();
    }
    if (tid < SCAN_GRID) g_bsum[tid] = sh[tid] - v;  // exclusive
    if (tid == 0) g_off[N_NODES] = N_EDGES;
}

// fixup: add block offsets, init cur + invdeg
__global__ void scan3_kernel() {
    int tid = threadIdx.x;
    int i = blockIdx.x * SCAN_BLK + tid;
    if (i < N_NODES) {
        int o = g_off[i] + g_bsum[blockIdx.x];
        g_off[i] = o;
        g_cur[i] = o;
        g_invdeg[i] = 1.0f / fmaxf((float)g_cnt[i], 1.0f);
    }
}

__global__ void fill_kernel(const int* __restrict__ e_src, const int* __restrict__ e_dst) {
    int e = blockIdx.x * blockDim.x + threadIdx.x;
    if (e < N_EDGES) {
        int d = e_dst[e];
        int pos = atomicAdd(&g_cur[d], 1);
        g_csr[pos] = e_src[e];
    }
}

// ---------------- mean aggregation (gather via CSR), float4 ----------------
// blockDim.x = F/4 channels-vec, blockDim.y = nodes per block
__global__ void aggregate_kernel(int layer) {
    const float4* feat = (const float4*)(layer ? g_h1 : g_h0);
    int Fv = (layer ? F1 : F0) >> 2;
    int n = blockIdx.x * blockDim.y + threadIdx.y;
    if (n >= N_NODES) return;
    int c = threadIdx.x;
    int s = g_off[n], e = g_off[n + 1];
    float4 acc = make_float4(0.f, 0.f, 0.f, 0.f);
    for (int j = s; j < e; ++j) {
        int srcn = g_csr[j];
        float4 v = feat[(long long)srcn * Fv + c];
        acc.x += v.x; acc.y += v.y; acc.z += v.z; acc.w += v.w;
    }
    float sc = g_invdeg[n];
    acc.x *= sc; acc.y *= sc; acc.z *= sc; acc.w *= sc;
    ((float4*)g_agg)[(long long)n * Fv + c] = acc;
}

// ---------------- fused dual GEMM: C = relu(agg@Wl + x@Wr + b), f32x2 packed ----------------
#define BM 128
#define BN 128
#define BK 16
#define AST (BM + 4)   // 132, keeps 16B alignment (528 % 16 == 0) and kills transpose conflicts

__global__ __launch_bounds__(256, 2)
void gemm_fused_kernel(const float* __restrict__ Wl,
                       const float* __restrict__ Wr,
                       const float* __restrict__ bias,
                       int layer) {
    const float* Xin = layer ? g_h1 : g_h0;
    float* C = layer ? g_z : g_h1;
    const int F = layer ? F1 : F0;
    const int T0 = F / BK;           // tiles in phase 0 (agg@Wl)
    const int T = 2 * T0;            // + phase 1 (x@Wr)

    __shared__ float As[2][BK][AST];
    __shared__ float Bs[2][BK][BN];

    const int tx = threadIdx.x;
    const int row0 = blockIdx.x * BM;
    const int col0 = blockIdx.y * BN;
    const int tm = tx >> 4;          // 0..15 -> rows tm*8..+7
    const int tn = tx & 15;          // 0..15 -> cols tn*8..+7

    unsigned long long acc2[8][4];
#pragma unroll
    for (int i = 0; i < 8; ++i)
#pragma unroll
        for (int j = 0; j < 4; ++j) acc2[i][j] = 0ull;

    // per-thread load coordinates
    const int a_row = tx >> 2;        // 0..63  (x2 iterations -> 128 rows)
    const int a_kq  = (tx & 3) * 4;   // k quad
    const int b_k   = tx >> 5;        // 0..7   (x2 -> 16)
    const int b_n4  = (tx & 31) * 4;  // col quad

    float4 ra[2], rb[2];

    // prologue: load tile 0
    {
        const float* Ap = g_agg;
        const float* Wp = Wl;
#pragma unroll
        for (int q = 0; q < 2; ++q) {
            int gm = row0 + a_row + q * 64;
            ra[q] = (gm < N_NODES) ? *(const float4*)&Ap[(long long)gm * F + a_kq]
                                   : make_float4(0.f, 0.f, 0.f, 0.f);
            rb[q] = *(const float4*)&Wp[(long long)(b_k + q * 8) * HID + col0 + b_n4];
        }
#pragma unroll
        for (int q = 0; q < 2; ++q) {
            As[0][a_kq + 0][a_row + q * 64] = ra[q].x;
            As[0][a_kq + 1][a_row + q * 64] = ra[q].y;
            As[0][a_kq + 2][a_row + q * 64] = ra[q].z;
            As[0][a_kq + 3][a_row + q * 64] = ra[q].w;
            *(float4*)&Bs[0][b_k + q * 8][b_n4] = rb[q];
        }
    }
    __syncthreads();

    for (int t = 0; t < T; ++t) {
        const int buf = t & 1;
        // prefetch tile t+1 from global
        if (t + 1 < T) {
            int tt = t + 1;
            const float* Ap = (tt < T0) ? g_agg : Xin;
            const float* Wp = (tt < T0) ? Wl : Wr;
            int k0 = ((tt < T0) ? tt : (tt - T0)) * BK;
#pragma unroll
            for (int q = 0; q < 2; ++q) {
                int gm = row0 + a_row + q * 64;
                ra[q] = (gm < N_NODES) ? *(const float4*)&Ap[(long long)gm * F + k0 + a_kq]
                                       : make_float4(0.f, 0.f, 0.f, 0.f);
                rb[q] = *(const float4*)&Wp[(long long)(k0 + b_k + q * 8) * HID + col0 + b_n4];
            }
        }
        // compute on buf
#pragma unroll
        for (int k = 0; k < BK; ++k) {
            float4 a0 = *(float4*)&As[buf][k][tm * 8];
            float4 a1 = *(float4*)&As[buf][k][tm * 8 + 4];
            ulonglong2 bb0 = *(ulonglong2*)&Bs[buf][k][tn * 8];
            ulonglong2 bb1 = *(ulonglong2*)&Bs[buf][k][tn * 8 + 4];
            unsigned long long b2[4] = {bb0.x, bb0.y, bb1.x, bb1.y};
            unsigned long long a2[8];
            PACK_DUP(a2[0], a0.x); PACK_DUP(a2[1], a0.y);
            PACK_DUP(a2[2], a0.z); PACK_DUP(a2[3], a0.w);
            PACK_DUP(a2[4], a1.x); PACK_DUP(a2[5], a1.y);
            PACK_DUP(a2[6], a1.z); PACK_DUP(a2[7], a1.w);
#pragma unroll
            for (int i = 0; i < 8; ++i)
#pragma unroll
                for (int j = 0; j < 4; ++j)
                    FMA2(acc2[i][j], a2[i], b2[j]);
        }
        // store prefetched tile into other buffer
        if (t + 1 < T) {
            const int nbuf = buf ^ 1;
#pragma unroll
            for (int q = 0; q < 2; ++q) {
                As[nbuf][a_kq + 0][a_row + q * 64] = ra[q].x;
                As[nbuf][a_kq + 1][a_row + q * 64] = ra[q].y;
                As[nbuf][a_kq + 2][a_row + q * 64] = ra[q].z;
                As[nbuf][a_kq + 3][a_row + q * 64] = ra[q].w;
                *(float4*)&Bs[nbuf][b_k + q * 8][b_n4] = rb[q];
            }
            __syncthreads();
        }
    }

    // epilogue: bias + relu + store
    float4 bv0 = *(const float4*)&bias[col0 + tn * 8];
    float4 bv1 = *(const float4*)&bias[col0 + tn * 8 + 4];
    float bcol[8] = {bv0.x, bv0.y, bv0.z, bv0.w, bv1.x, bv1.y, bv1.z, bv1.w};
#pragma unroll
    for (int i = 0; i < 8; ++i) {
        int gm = row0 + tm * 8 + i;
        if (gm < N_NODES) {
            float r[8];
#pragma unroll
            for (int j = 0; j < 4; ++j) {
                unsigned int lo, hi;
                UNPACK2(lo, hi, acc2[i][j]);
                r[2 * j]     = __uint_as_float(lo);
                r[2 * j + 1] = __uint_as_float(hi);
            }
#pragma unroll
            for (int j = 0; j < 8; ++j) r[j] = fmaxf(r[j] + bcol[j], 0.f);
            float* crow = C + (long long)gm * HID + col0 + tn * 8;
            *(float4*)crow       = make_float4(r[0], r[1], r[2], r[3]);
            *(float4*)(crow + 4) = make_float4(r[4], r[5], r[6], r[7]);
        }
    }
}

// ---------------- pair scoring: sigmoid(dot(z[src], z[dst])) ----------------
__global__ void pair_kernel(const int* __restrict__ src,
                            const int* __restrict__ dst,
                            float* __restrict__ out) {
    int gw = (blockIdx.x * blockDim.x + threadIdx.x) >> 5;
    int lane = threadIdx.x & 31;
    if (gw >= N_PAIRS) return;
    int a = src[gw], b = dst[gw];
    const float4* za = (const float4*)(g_z + (long long)a * HID);
    const float4* zb = (const float4*)(g_z + (long long)b * HID);
    float acc = 0.f;
#pragma unroll
    for (int i = 0; i < 2; ++i) {
        float4 va = za[lane + i * 32];
        float4 vb = zb[lane + i * 32];
        acc += va.x * vb.x + va.y * vb.y + va.z * vb.z + va.w * vb.w;
    }
#pragma unroll
    for (int o = 16; o; o >>= 1) acc += __shfl_xor_sync(0xFFFFFFFFu, acc, o);
    if (lane == 0) out[gw] = 1.f / (1.f + expf(-acc));
}

// ---------------- launch ----------------
extern "C" void kernel_launch(void* const* d_in, const int* in_sizes, int n_in,
                              void* d_out, int out_size) {
    const float* x           = (const float*)d_in[0];
    const int*   tok_ids     = (const int*)  d_in[1];
    const float* scores      = (const float*)d_in[2];
    const int*   cat_ids     = (const int*)  d_in[3];
    const int*   edge_index  = (const int*)  d_in[4];
    const int*   src         = (const int*)  d_in[5];
    const int*   dst         = (const int*)  d_in[6];
    const float* trait_embed = (const float*)d_in[7];
    const float* cat_embed   = (const float*)d_in[8];
    const float* proj_W      = (const float*)d_in[9];
    const float* proj_b      = (const float*)d_in[10];
    const float* W_l0        = (const float*)d_in[11];
    const float* b_l0        = (const float*)d_in[12];
    const float* W_r0        = (const float*)d_in[13];
    const float* W_l1        = (const float*)d_in[14];
    const float* b_l1        = (const float*)d_in[15];
    const float* W_r1        = (const float*)d_in[16];
    float* out = (float*)d_out;

    const int* e_src = edge_index;
    const int* e_dst = edge_index + N_EDGES;

    gwas_kernel<<<(N_NODES + 7) / 8, 256>>>(x, tok_ids, scores, cat_ids,
                                            trait_embed, cat_embed, proj_W, proj_b);

    zero_cnt_kernel<<<(N_NODES + 255) / 256, 256>>>();
    count_kernel<<<(N_EDGES + 255) / 256, 256>>>(e_dst);
    scan1_kernel<<<SCAN_GRID, SCAN_BLK>>>();
    scan2_kernel<<<1, SCAN_BLK>>>();
    scan3_kernel<<<SCAN_GRID, SCAN_BLK>>>();
    fill_kernel<<<(N_EDGES + 255) / 256, 256>>>(e_src, e_dst);

    // Layer 0
    {
        dim3 blk(F0 / 4, 6);
        aggregate_kernel<<<(N_NODES + 5) / 6, blk>>>(0);
        dim3 grid((N_NODES + BM - 1) / BM, HID / BN);
        gemm_fused_kernel<<<grid, 256>>>(W_l0, W_r0, b_l0, 0);
    }

    // Layer 1
    {
        dim3 blk(F1 / 4, 4);
        aggregate_kernel<<<(N_NODES + 3) / 4, blk>>>(1);
        dim3 grid((N_NODES + BM - 1) / BM, HID / BN);
        gemm_fused_kernel<<<grid, 256>>>(W_l1, W_r1, b_l1, 1);
    }

    pair_kernel<<<(N_PAIRS * 32 + 255) / 256, 256>>>(src, dst, out);
}

// round 4
// speedup vs baseline: 3.1899x; 1.5185x over previous
#include <cuda_runtime.h>
#include <cuda_bf16.h>
#include <math.h>
#include <stdint.h>

#define N_NODES 50000
#define N_EDGES 800000
#define N_PAIRS 100000
#define IN_CH 128
#define HID 256
#define EMB 32
#define CAT_EMB 8
#define MAX_TOK 20
#define F0 160   // IN_CH + EMB
#define F1 256   // HID

// ---------------- scratch (static __device__ arrays; no allocation) ----------------
__device__ float g_h0[N_NODES * F0];    // concat(x, gwas_feat)
__device__ float g_agg[N_NODES * F1];   // aggregation scratch (sized for max F)
__device__ float g_h1[N_NODES * F1];    // layer-0 output
__device__ float g_z[N_NODES * F1];     // layer-1 output
__device__ int   g_cnt[N_NODES];
__device__ int   g_off[N_NODES + 1];
__device__ int   g_cur[N_NODES];
__device__ int   g_csr[N_EDGES];
__device__ float g_invdeg[N_NODES];

// pre-split, pre-transposed weights: slot = layer*2 + (0:W_l, 1:W_r); layout [n][k]
__device__ __nv_bfloat16 g_wt_hi[4][256 * 256];
__device__ __nv_bfloat16 g_wt_lo[4][256 * 256];

#define SCAN_BLK 256
#define SCAN_GRID ((N_NODES + SCAN_BLK - 1) / SCAN_BLK)
__device__ int g_bsum[SCAN_GRID];

// ================= mma.sync helpers =================
__device__ __forceinline__ uint32_t smem_u32(const void* p) {
    uint32_t a;
    asm("{ .reg .u64 t; cvta.to.shared.u64 t, %1; cvt.u32.u64 %0, t; }" : "=r"(a) : "l"(p));
    return a;
}
__device__ __forceinline__ void ldmx4(uint32_t* r, uint32_t addr) {
    asm volatile("ldmatrix.sync.aligned.m8n8.x4.shared.b16 {%0,%1,%2,%3}, [%4];"
                 : "=r"(r[0]), "=r"(r[1]), "=r"(r[2]), "=r"(r[3]) : "r"(addr));
}
__device__ __forceinline__ void hmma(float* c, const uint32_t* a, const uint32_t* b) {
    asm volatile("mma.sync.aligned.m16n8k16.row.col.f32.bf16.bf16.f32 "
                 "{%0,%1,%2,%3}, {%4,%5,%6,%7}, {%8,%9}, {%0,%1,%2,%3};"
                 : "+f"(c[0]), "+f"(c[1]), "+f"(c[2]), "+f"(c[3])
                 : "r"(a[0]), "r"(a[1]), "r"(a[2]), "r"(a[3]), "r"(b[0]), "r"(b[1]));
}

// smem stage layout (bf16, row stride 40 elems = 80B -> conflict-free ldmatrix)
#define ASTR 40
#define A_HI 0
#define A_LO 10240
#define B_HI 20480
#define B_LO 30720
#define STAGE_BYTES 40960
#define SMEM_GEMM_TOTAL (2 * STAGE_BYTES)   // 80 KB

// ---------------- GWAS encoder + concat into h0 ----------------
__global__ void gwas_kernel(const float* __restrict__ x,
                            const int* __restrict__ tok,
                            const float* __restrict__ scores,
                            const int* __restrict__ cat,
                            const float* __restrict__ trait_embed,
                            const float* __restrict__ cat_embed,
                            const float* __restrict__ proj_W,
                            const float* __restrict__ proj_b) {
    int warp_in_block = threadIdx.x >> 5;
    int lane = threadIdx.x & 31;
    int n = blockIdx.x * (blockDim.x >> 5) + warp_in_block;
    if (n >= N_NODES) return;

    __shared__ float sh_acc[8][41];
    float acc_trait = 0.f, acc_cat = 0.f, acc_s = 0.f, wsum = 0.f;

    const int*   tk = tok    + (long long)n * MAX_TOK;
    const float* sc = scores + (long long)n * MAX_TOK;
    const int*   ct = cat    + (long long)n * MAX_TOK;

    for (int t = 0; t < MAX_TOK; ++t) {
        int   tid = tk[t];
        float s   = sc[t];
        int   cid = ct[t];
        float w   = (tid != 0) ? s : 0.f;
        wsum += w;
        acc_trait += w * trait_embed[tid * EMB + lane];
        if (lane < CAT_EMB) acc_cat += w * cat_embed[cid * CAT_EMB + lane];
        acc_s += w * s;
    }
    sh_acc[warp_in_block][lane] = acc_trait;
    if (lane < CAT_EMB) sh_acc[warp_in_block][EMB + lane] = acc_cat;
    if (lane == 0)      sh_acc[warp_in_block][EMB + CAT_EMB] = acc_s;
    __syncwarp();

    float inv = 1.f / fmaxf(wsum, 1e-8f);
    float o = wsum * proj_b[lane];
    const float* shv = sh_acc[warp_in_block];
#pragma unroll
    for (int k = 0; k < 41; ++k)
        o += shv[k] * proj_W[k * EMB + lane];

    float* hrow = g_h0 + (long long)n * F0;
    hrow[IN_CH + lane] = o * inv;
    const float* xrow = x + (long long)n * IN_CH;
#pragma unroll
    for (int i = 0; i < 4; ++i)
        hrow[lane + i * 32] = xrow[lane + i * 32];
}

// ---------------- weight transpose + bf16 hi/lo split ----------------
__global__ void wsplit_kernel(const float* __restrict__ W, int K, int slot) {
    int idx = blockIdx.x * blockDim.x + threadIdx.x;
    if (idx >= K * 256) return;
    int k = idx >> 8, n = idx & 255;
    float v = W[k * 256 + n];
    __nv_bfloat16 h = __float2bfloat16_rn(v);
    float r = v - __bfloat162float(h);
    g_wt_hi[slot][n * K + k] = h;
    g_wt_lo[slot][n * K + k] = __float2bfloat16_rn(r);
}

// ---------------- CSR build ----------------
__global__ void zero_cnt_kernel() {
    int i = blockIdx.x * blockDim.x + threadIdx.x;
    if (i < N_NODES) g_cnt[i] = 0;
}
__global__ void count_kernel(const int* __restrict__ e_dst) {
    int e = blockIdx.x * blockDim.x + threadIdx.x;
    if (e < N_EDGES) atomicAdd(&g_cnt[e_dst[e]], 1);
}
__global__ void scan1_kernel() {
    __shared__ int sh[SCAN_BLK];
    int tid = threadIdx.x;
    int i = blockIdx.x * SCAN_BLK + tid;
    int v = (i < N_NODES) ? g_cnt[i] : 0;
    sh[tid] = v;
    __syncthreads();
#pragma unroll
    for (int off = 1; off < SCAN_BLK; off <<= 1) {
        int t = (tid >= off) ? sh[tid - off] : 0;
        __syncthreads();
        sh[tid] += t;
        __syncthreads();
    }
    if (i < N_NODES) g_off[i] = sh[tid] - v;
    if (tid == SCAN_BLK - 1) g_bsum[blockIdx.x] = sh[tid];
}
__global__ void scan2_kernel() {
    __shared__ int sh[SCAN_BLK];
    int tid = threadIdx.x;
    int v = (tid < SCAN_GRID) ? g_bsum[tid] : 0;
    sh[tid] = v;
    __syncthreads();
#pragma unroll
    for (int off = 1; off < SCAN_BLK; off <<= 1) {
        int t = (tid >= off) ? sh[tid - off] : 0;
        __syncthreads();
        sh[tid] += t;
        __syncthreads();
    }
    if (tid < SCAN_GRID) g_bsum[tid] = sh[tid] - v;
    if (tid == 0) g_off[N_NODES] = N_EDGES;
}
__global__ void scan3_kernel() {
    int tid = threadIdx.x;
    int i = blockIdx.x * SCAN_BLK + tid;
    if (i < N_NODES) {
        int o = g_off[i] + g_bsum[blockIdx.x];
        g_off[i] = o;
        g_cur[i] = o;
        g_invdeg[i] = 1.0f / fmaxf((float)g_cnt[i], 1.0f);
    }
}
__global__ void fill_kernel(const int* __restrict__ e_src, const int* __restrict__ e_dst) {
    int e = blockIdx.x * blockDim.x + threadIdx.x;
    if (e < N_EDGES) {
        int d = e_dst[e];
        int pos = atomicAdd(&g_cur[d], 1);
        g_csr[pos] = e_src[e];
    }
}

// ---------------- mean aggregation (gather via CSR), float4 ----------------
__global__ void aggregate_kernel(int layer) {
    const float4* feat = (const float4*)(layer ? g_h1 : g_h0);
    int Fv = (layer ? F1 : F0) >> 2;
    int n = blockIdx.x * blockDim.y + threadIdx.y;
    if (n >= N_NODES) return;
    int c = threadIdx.x;
    int s = g_off[n], e = g_off[n + 1];
    float4 acc = make_float4(0.f, 0.f, 0.f, 0.f);
    for (int j = s; j < e; ++j) {
        int srcn = g_csr[j];
        float4 v = feat[(long long)srcn * Fv + c];
        acc.x += v.x; acc.y += v.y; acc.z += v.z; acc.w += v.w;
    }
    float sc = g_invdeg[n];
    acc.x *= sc; acc.y *= sc; acc.z *= sc; acc.w *= sc;
    ((float4*)g_agg)[(long long)n * Fv + c] = acc;
}

// ---------------- tensor-core GEMM (mma.sync bf16 x3 error-split) ----------------
// C[128x128 per CTA] = relu(agg@Wl + x@Wr + b); fp32 accum.
struct Pref {
    float4 a[4];
    uint4  bh[2], bl[2];
};

__device__ __forceinline__ void ldg_chunk(Pref& p, int layer, int F, int nc,
                                          int t, int row0, int col0) {
    int half = (t >= nc) ? 1 : 0;
    int k0 = (t - half * nc) * 32;
    const float* Asrc = half ? (layer ? g_h1 : g_h0) : g_agg;
    int slot = layer * 2 + half;
    const __nv_bfloat16* Bh = g_wt_hi[slot];
    const __nv_bfloat16* Bl = g_wt_lo[slot];
    int tid = threadIdx.x;
#pragma unroll
    for (int j = 0; j < 4; ++j) {
        int i = tid + j * 256;
        int r = i >> 3, q = i & 7;
        int gm = row0 + r;
        p.a[j] = (gm < N_NODES) ? *(const float4*)(Asrc + (size_t)gm * F + k0 + q * 4)
                                : make_float4(0.f, 0.f, 0.f, 0.f);
    }
#pragma unroll
    for (int j = 0; j < 2; ++j) {
        int i = tid + j * 256;
        int r = i >> 2, o = (i & 3) * 8;
        size_t off = (size_t)(col0 + r) * F + k0 + o;
        p.bh[j] = *(const uint4*)(Bh + off);
        p.bl[j] = *(const uint4*)(Bl + off);
    }
}

__device__ __forceinline__ void sts_chunk(const Pref& p, char* stage) {
    int tid = threadIdx.x;
#pragma unroll
    for (int j = 0; j < 4; ++j) {
        int i = tid + j * 256;
        int r = i >> 3, q = i & 7;
        float4 v = p.a[j];
        __nv_bfloat162 h01 = __floats2bfloat162_rn(v.x, v.y);
        __nv_bfloat162 h23 = __floats2bfloat162_rn(v.z, v.w);
        float2 f01 = __bfloat1622float2(h01);
        float2 f23 = __bfloat1622float2(h23);
        __nv_bfloat162 l01 = __floats2bfloat162_rn(v.x - f01.x, v.y - f01.y);
        __nv_bfloat162 l23 = __floats2bfloat162_rn(v.z - f23.x, v.w - f23.y);
        uint32_t off = (uint32_t)(r * (ASTR * 2) + q * 8);
        *(uint2*)(stage + A_HI + off) = make_uint2(*(uint32_t*)&h01, *(uint32_t*)&h23);
        *(uint2*)(stage + A_LO + off) = make_uint2(*(uint32_t*)&l01, *(uint32_t*)&l23);
    }
#pragma unroll
    for (int j = 0; j < 2; ++j) {
        int i = tid + j * 256;
        int r = i >> 2, o = (i & 3) * 8;
        uint32_t off = (uint32_t)(r * (ASTR * 2) + o * 2);
        *(uint4*)(stage + B_HI + off) = p.bh[j];
        *(uint4*)(stage + B_LO + off) = p.bl[j];
    }
}

__global__ __launch_bounds__(256)
void gemm_mma_kernel(const float* __restrict__ bias, int layer) {
    extern __shared__ char smem[];
    const int F  = layer ? F1 : F0;
    const int nc = F / 32;
    const int T  = 2 * nc;
    const int row0 = blockIdx.x * 128;
    const int col0 = blockIdx.y * 128;
    float* C = layer ? g_z : g_h1;

    const int tid = threadIdx.x, wid = tid >> 5, lane = tid & 31;
    const int wm0 = (wid >> 2) * 64;   // warp row offset within CTA
    const int wn0 = (wid & 3) * 32;    // warp col offset within CTA

    float acc[4][4][4];
#pragma unroll
    for (int a = 0; a < 4; ++a)
#pragma unroll
        for (int b = 0; b < 4; ++b)
#pragma unroll
            for (int c = 0; c < 4; ++c) acc[a][b][c] = 0.f;

    Pref p;
    ldg_chunk(p, layer, F, nc, 0, row0, col0);
    sts_chunk(p, smem);
    __syncthreads();

    // ldmatrix address components (constant across chunks)
    const uint32_t sbase = smem_u32(smem);
    const int b_row = ((lane >> 4) & 1) * 8 + (lane & 7);
    const int b_khalf = ((lane >> 3) & 1) * 8;
    const int a_row = lane & 15;
    const int a_khalf = ((lane >> 4) & 1) * 8;

    for (int t = 0; t < T; ++t) {
        if (t + 1 < T) ldg_chunk(p, layer, F, nc, t + 1, row0, col0);
        const uint32_t sb = sbase + (uint32_t)(t & 1) * STAGE_BYTES;
#pragma unroll
        for (int ks = 0; ks < 2; ++ks) {
            uint32_t bhi[4][2], blo[4][2];
            {
                uint32_t r[4];
                uint32_t ad = sb + B_HI + (uint32_t)((wn0 + b_row) * (ASTR * 2) + (ks * 16 + b_khalf) * 2);
                ldmx4(r, ad);
                bhi[0][0] = r[0]; bhi[0][1] = r[1]; bhi[1][0] = r[2]; bhi[1][1] = r[3];
                ldmx4(r, ad + 16 * (ASTR * 2));
                bhi[2][0] = r[0]; bhi[2][1] = r[1]; bhi[3][0] = r[2]; bhi[3][1] = r[3];
                uint32_t ad2 = sb + B_LO + (uint32_t)((wn0 + b_row) * (ASTR * 2) + (ks * 16 + b_khalf) * 2);
                ldmx4(r, ad2);
                blo[0][0] = r[0]; blo[0][1] = r[1]; blo[1][0] = r[2]; blo[1][1] = r[3];
                ldmx4(r, ad2 + 16 * (ASTR * 2));
                blo[2][0] = r[0]; blo[2][1] = r[1]; blo[3][0] = r[2]; blo[3][1] = r[3];
            }
            uint32_t ahi[4][4], alo[4][4];
#pragma unroll
            for (int mt = 0; mt < 4; ++mt) {
                uint32_t roff = (uint32_t)((wm0 + mt * 16 + a_row) * (ASTR * 2) + (ks * 16 + a_khalf) * 2);
                ldmx4(ahi[mt], sb + A_HI + roff);
                ldmx4(alo[mt], sb + A_LO + roff);
            }
#pragma unroll
            for (int mt = 0; mt < 4; ++mt)
#pragma unroll
                for (int nt = 0; nt < 4; ++nt) {
                    hmma(acc[mt][nt], ahi[mt], bhi[nt]);
                    hmma(acc[mt][nt], alo[mt], bhi[nt]);
                    hmma(acc[mt][nt], ahi[mt], blo[nt]);
                }
        }
        if (t + 1 < T) sts_chunk(p, smem + ((t + 1) & 1) * STAGE_BYTES);
        __syncthreads();
    }

    // epilogue: bias + relu + store
#pragma unroll
    for (int mt = 0; mt < 4; ++mt) {
        int rbase = row0 + wm0 + mt * 16 + (lane >> 2);
#pragma unroll
        for (int half = 0; half < 2; ++half) {
            int gm = rbase + half * 8;
            if (gm < N_NODES) {
                float* crow = C + (size_t)gm * HID;
#pragma unroll
                for (int nt = 0; nt < 4; ++nt) {
                    int cn = col0 + wn0 + nt * 8 + (lane & 3) * 2;
                    float v0 = acc[mt][nt][half * 2]     + bias[cn];
                    float v1 = acc[mt][nt][half * 2 + 1] + bias[cn + 1];
                    *(float2*)(crow + cn) = make_float2(fmaxf(v0, 0.f), fmaxf(v1, 0.f));
                }
            }
        }
    }
}

// ---------------- pair scoring ----------------
__global__ void pair_kernel(const int* __restrict__ src,
                            const int* __restrict__ dst,
                            float* __restrict__ out) {
    int gw = (blockIdx.x * blockDim.x + threadIdx.x) >> 5;
    int lane = threadIdx.x & 31;
    if (gw >= N_PAIRS) return;
    int a = src[gw], b = dst[gw];
    const float4* za = (const float4*)(g_z + (long long)a * HID);
    const float4* zb = (const float4*)(g_z + (long long)b * HID);
    float acc = 0.f;
#pragma unroll
    for (int i = 0; i < 2; ++i) {
        float4 va = za[lane + i * 32];
        float4 vb = zb[lane + i * 32];
        acc += va.x * vb.x + va.y * vb.y + va.z * vb.z + va.w * vb.w;
    }
#pragma unroll
    for (int o = 16; o; o >>= 1) acc += __shfl_xor_sync(0xFFFFFFFFu, acc, o);
    if (lane == 0) out[gw] = 1.f / (1.f + expf(-acc));
}

// ---------------- launch ----------------
extern "C" void kernel_launch(void* const* d_in, const int* in_sizes, int n_in,
                              void* d_out, int out_size) {
    const float* x           = (const float*)d_in[0];
    const int*   tok_ids     = (const int*)  d_in[1];
    const float* scores      = (const float*)d_in[2];
    const int*   cat_ids     = (const int*)  d_in[3];
    const int*   edge_index  = (const int*)  d_in[4];
    const int*   src         = (const int*)  d_in[5];
    const int*   dst         = (const int*)  d_in[6];
    const float* trait_embed = (const float*)d_in[7];
    const float* cat_embed   = (const float*)d_in[8];
    const float* proj_W      = (const float*)d_in[9];
    const float* proj_b      = (const float*)d_in[10];
    const float* W_l0        = (const float*)d_in[11];
    const float* b_l0        = (const float*)d_in[12];
    const float* W_r0        = (const float*)d_in[13];
    const float* W_l1        = (const float*)d_in[14];
    const float* b_l1        = (const float*)d_in[15];
    const float* W_r1        = (const float*)d_in[16];
    float* out = (float*)d_out;

    const int* e_src = edge_index;
    const int* e_dst = edge_index + N_EDGES;

    cudaFuncSetAttribute(gemm_mma_kernel,
                         cudaFuncAttributeMaxDynamicSharedMemorySize, SMEM_GEMM_TOTAL);

    gwas_kernel<<<(N_NODES + 7) / 8, 256>>>(x, tok_ids, scores, cat_ids,
                                            trait_embed, cat_embed, proj_W, proj_b);

    wsplit_kernel<<<(F0 * 256 + 255) / 256, 256>>>(W_l0, F0, 0);
    wsplit_kernel<<<(F0 * 256 + 255) / 256, 256>>>(W_r0, F0, 1);
    wsplit_kernel<<<(F1 * 256 + 255) / 256, 256>>>(W_l1, F1, 2);
    wsplit_kernel<<<(F1 * 256 + 255) / 256, 256>>>(W_r1, F1, 3);

    zero_cnt_kernel<<<(N_NODES + 255) / 256, 256>>>();
    count_kernel<<<(N_EDGES + 255) / 256, 256>>>(e_dst);
    scan1_kernel<<<SCAN_GRID, SCAN_BLK>>>();
    scan2_kernel<<<1, SCAN_BLK>>>();
    scan3_kernel<<<SCAN_GRID, SCAN_BLK>>>();
    fill_kernel<<<(N_EDGES + 255) / 256, 256>>>(e_src, e_dst);

    const dim3 ggrid((N_NODES + 127) / 128, 2);

    // Layer 0
    {
        dim3 blk(F0 / 4, 6);
        aggregate_kernel<<<(N_NODES + 5) / 6, blk>>>(0);
        gemm_mma_kernel<<<ggrid, 256, SMEM_GEMM_TOTAL>>>(b_l0, 0);
    }
    // Layer 1
    {
        dim3 blk(F1 / 4, 4);
        aggregate_kernel<<<(N_NODES + 3) / 4, blk>>>(1);
        gemm_mma_kernel<<<ggrid, 256, SMEM_GEMM_TOTAL>>>(b_l1, 1);
    }

    pair_kernel<<<(N_PAIRS * 32 + 255) / 256, 256>>>(src, dst, out);
}

// round 5
// speedup vs baseline: 4.7843x; 1.4999x over previous
#include <cuda_runtime.h>
#include <cuda_fp16.h>
#include <math.h>
#include <stdint.h>

#define N_NODES 50000
#define N_EDGES 800000
#define N_PAIRS 100000
#define IN_CH 128
#define HID 256
#define EMB 32
#define CAT_EMB 8
#define MAX_TOK 20
#define F0 160   // IN_CH + EMB
#define F1 256   // HID

// ---------------- scratch (fp16 feature tables, fp32 accumulation) ----------------
__device__ __half g_h0h[N_NODES * F0];
__device__ __half g_aggh[N_NODES * F1];
__device__ __half g_h1h[N_NODES * F1];
__device__ __half g_zh[N_NODES * F1];
__device__ int    g_cnt[N_NODES];
__device__ int    g_off[N_NODES + 1];
__device__ int    g_cur[N_NODES];
__device__ int    g_csr[N_EDGES];
__device__ float  g_invdeg[N_NODES];

// pre-split, pre-transposed weights: slot = layer*2 + (0:W_l, 1:W_r); layout [n][k], fp16 hi/lo
__device__ __half g_wt_hi[4][256 * 256];
__device__ __half g_wt_lo[4][256 * 256];

#define SCAN_BLK 256
#define SCAN_GRID ((N_NODES + SCAN_BLK - 1) / SCAN_BLK)
__device__ int g_bsum[SCAN_GRID];

// ================= mma.sync helpers =================
__device__ __forceinline__ uint32_t smem_u32(const void* p) {
    uint32_t a;
    asm("{ .reg .u64 t; cvta.to.shared.u64 t, %1; cvt.u32.u64 %0, t; }" : "=r"(a) : "l"(p));
    return a;
}
__device__ __forceinline__ void ldmx4(uint32_t* r, uint32_t addr) {
    asm volatile("ldmatrix.sync.aligned.m8n8.x4.shared.b16 {%0,%1,%2,%3}, [%4];"
                 : "=r"(r[0]), "=r"(r[1]), "=r"(r[2]), "=r"(r[3]) : "r"(addr));
}
__device__ __forceinline__ void hmma(float* c, const uint32_t* a, const uint32_t* b) {
    asm volatile("mma.sync.aligned.m16n8k16.row.col.f32.f16.f16.f32 "
                 "{%0,%1,%2,%3}, {%4,%5,%6,%7}, {%8,%9}, {%0,%1,%2,%3};"
                 : "+f"(c[0]), "+f"(c[1]), "+f"(c[2]), "+f"(c[3])
                 : "r"(a[0]), "r"(a[1]), "r"(a[2]), "r"(a[3]), "r"(b[0]), "r"(b[1]));
}

// smem stage layout (fp16, row stride 40 elems = 80B -> conflict-free ldmatrix)
#define ASTR2 80        // row stride in bytes
#define A_H  0
#define B_HI 10240
#define B_LO 20480
#define STAGE_BYTES 30720
#define SMEM_GEMM_TOTAL (2 * STAGE_BYTES)   // 60 KB

// ---------------- GWAS encoder + concat into h0 (fp16) ----------------
__global__ void gwas_kernel(const float* __restrict__ x,
                            const int* __restrict__ tok,
                            const float* __restrict__ scores,
                            const int* __restrict__ cat,
                            const float* __restrict__ trait_embed,
                            const float* __restrict__ cat_embed,
                            const float* __restrict__ proj_W,
                            const float* __restrict__ proj_b) {
    int warp_in_block = threadIdx.x >> 5;
    int lane = threadIdx.x & 31;
    int n = blockIdx.x * (blockDim.x >> 5) + warp_in_block;
    if (n >= N_NODES) return;

    __shared__ float sh_acc[8][41];
    float acc_trait = 0.f, acc_cat = 0.f, acc_s = 0.f, wsum = 0.f;

    const int*   tk = tok    + (long long)n * MAX_TOK;
    const float* sc = scores + (long long)n * MAX_TOK;
    const int*   ct = cat    + (long long)n * MAX_TOK;

    for (int t = 0; t < MAX_TOK; ++t) {
        int   tid = tk[t];
        float s   = sc[t];
        int   cid = ct[t];
        float w   = (tid != 0) ? s : 0.f;
        wsum += w;
        acc_trait += w * trait_embed[tid * EMB + lane];
        if (lane < CAT_EMB) acc_cat += w * cat_embed[cid * CAT_EMB + lane];
        acc_s += w * s;
    }
    sh_acc[warp_in_block][lane] = acc_trait;
    if (lane < CAT_EMB) sh_acc[warp_in_block][EMB + lane] = acc_cat;
    if (lane == 0)      sh_acc[warp_in_block][EMB + CAT_EMB] = acc_s;
    __syncwarp();

    float inv = 1.f / fmaxf(wsum, 1e-8f);
    float o = wsum * proj_b[lane];
    const float* shv = sh_acc[warp_in_block];
#pragma unroll
    for (int k = 0; k < 41; ++k)
        o += shv[k] * proj_W[k * EMB + lane];

    __half* hrow = g_h0h + (long long)n * F0;
    hrow[IN_CH + lane] = __float2half_rn(o * inv);
    const float* xrow = x + (long long)n * IN_CH;
#pragma unroll
    for (int i = 0; i < 4; ++i)
        hrow[lane + i * 32] = __float2half_rn(xrow[lane + i * 32]);
}

// ---------------- weight transpose + fp16 hi/lo split (all 4 slots, one kernel) ----------------
__global__ void wsplit_all_kernel(const float* __restrict__ Wl0, const float* __restrict__ Wr0,
                                  const float* __restrict__ Wl1, const float* __restrict__ Wr1) {
    int idx = blockIdx.x * blockDim.x + threadIdx.x;
    if (idx >= 256 * 256) return;
    int n = idx & 255, j = idx >> 8;   // j = k index
    const float* Ws[4] = {Wl0, Wr0, Wl1, Wr1};
    const int    Ks[4] = {F0, F0, F1, F1};
#pragma unroll
    for (int slot = 0; slot < 4; ++slot) {
        int K = Ks[slot];
        if (j < K) {
            float v = Ws[slot][j * 256 + n];
            __half h = __float2half_rn(v);
            g_wt_hi[slot][n * K + j] = h;
            g_wt_lo[slot][n * K + j] = __float2half_rn(v - __half2float(h));
        }
    }
}

// ---------------- CSR build ----------------
__global__ void zero_cnt_kernel() {
    int i = blockIdx.x * blockDim.x + threadIdx.x;
    if (i < N_NODES) g_cnt[i] = 0;
}
__global__ void count_kernel(const int* __restrict__ e_dst) {
    int e = blockIdx.x * blockDim.x + threadIdx.x;
    if (e < N_EDGES) atomicAdd(&g_cnt[e_dst[e]], 1);
}
__global__ void scan1_kernel() {
    __shared__ int sh[SCAN_BLK];
    int tid = threadIdx.x;
    int i = blockIdx.x * SCAN_BLK + tid;
    int v = (i < N_NODES) ? g_cnt[i] : 0;
    sh[tid] = v;
    __syncthreads();
#pragma unroll
    for (int off = 1; off < SCAN_BLK; off <<= 1) {
        int t = (tid >= off) ? sh[tid - off] : 0;
        __syncthreads();
        sh[tid] += t;
        __syncthreads();
    }
    if (i < N_NODES) g_off[i] = sh[tid] - v;
    if (tid == SCAN_BLK - 1) g_bsum[blockIdx.x] = sh[tid];
}
__global__ void scan2_kernel() {
    __shared__ int sh[SCAN_BLK];
    int tid = threadIdx.x;
    int v = (tid < SCAN_GRID) ? g_bsum[tid] : 0;
    sh[tid] = v;
    __syncthreads();
#pragma unroll
    for (int off = 1; off < SCAN_BLK; off <<= 1) {
        int t = (tid >= off) ? sh[tid - off] : 0;
        __syncthreads();
        sh[tid] += t;
        __syncthreads();
    }
    if (tid < SCAN_GRID) g_bsum[tid] = sh[tid] - v;
    if (tid == 0) g_off[N_NODES] = N_EDGES;
}
__global__ void scan3_kernel() {
    int tid = threadIdx.x;
    int i = blockIdx.x * SCAN_BLK + tid;
    if (i < N_NODES) {
        int o = g_off[i] + g_bsum[blockIdx.x];
        g_off[i] = o;
        g_cur[i] = o;
        g_invdeg[i] = 1.0f / fmaxf((float)g_cnt[i], 1.0f);
    }
}
__global__ void fill_kernel(const int* __restrict__ e_src, const int* __restrict__ e_dst) {
    int e = blockIdx.x * blockDim.x + threadIdx.x;
    if (e < N_EDGES) {
        int d = e_dst[e];
        int pos = atomicAdd(&g_cur[d], 1);
        g_csr[pos] = e_src[e];
    }
}

// ---------------- mean aggregation (fp16 gather, fp32 accum, fp16 store) ----------------
// thread handles 8 channels (one uint4 = 8 halves); blockDim.x = F/8, blockDim.y nodes/blk
__global__ void aggregate_kernel(int layer) {
    const uint4* feat = (const uint4*)(layer ? g_h1h : g_h0h);
    int Fv8 = (layer ? F1 : F0) >> 3;
    int n = blockIdx.x * blockDim.y + threadIdx.y;
    if (n >= N_NODES) return;
    int c = threadIdx.x;
    int s = g_off[n], e = g_off[n + 1];
    float acc[8];
#pragma unroll
    for (int i = 0; i < 8; ++i) acc[i] = 0.f;
    for (int j = s; j < e; ++j) {
        int srcn = g_csr[j];
        uint4 v = feat[(size_t)srcn * Fv8 + c];
        const __half2* hv = (const __half2*)&v;
#pragma unroll
        for (int i = 0; i < 4; ++i) {
            float2 f = __half22float2(hv[i]);
            acc[2 * i]     += f.x;
            acc[2 * i + 1] += f.y;
        }
    }
    float sc = g_invdeg[n];
    uint4 outv;
    __half2* ho = (__half2*)&outv;
#pragma unroll
    for (int i = 0; i < 4; ++i)
        ho[i] = __floats2half2_rn(acc[2 * i] * sc, acc[2 * i + 1] * sc);
    ((uint4*)g_aggh)[(size_t)n * Fv8 + c] = outv;
}

// ---------------- tensor-core GEMM: C = relu(agg@Wl + x@Wr + b), fp16 A, B hi/lo ----------------
struct Pref {
    uint4 a[2], bh[2], bl[2];
};

__device__ __forceinline__ void ldg_chunk(Pref& p, int layer, int F, int nc,
                                          int t, int row0, int col0) {
    int hf = (t >= nc) ? 1 : 0;
    int k0 = (t - hf * nc) * 32;
    const __half* Asrc = hf ? (layer ? g_h1h : g_h0h) : g_aggh;
    int slot = layer * 2 + hf;
    const __half* Bh = g_wt_hi[slot];
    const __half* Bl = g_wt_lo[slot];
    int tid = threadIdx.x;
#pragma unroll
    for (int j = 0; j < 2; ++j) {
        int i = tid + j * 256;
        int r = i >> 2, q8 = (i & 3) * 8;
        int gm = row0 + r;
        p.a[j] = (gm < N_NODES) ? *(const uint4*)(Asrc + (size_t)gm * F + k0 + q8)
                                : make_uint4(0, 0, 0, 0);
    }
#pragma unroll
    for (int j = 0; j < 2; ++j) {
        int i = tid + j * 256;
        int r = i >> 2, o8 = (i & 3) * 8;
        size_t off = (size_t)(col0 + r) * F + k0 + o8;
        p.bh[j] = *(const uint4*)(Bh + off);
        p.bl[j] = *(const uint4*)(Bl + off);
    }
}

__device__ __forceinline__ void sts_chunk(const Pref& p, char* stage) {
    int tid = threadIdx.x;
#pragma unroll
    for (int j = 0; j < 2; ++j) {
        int i = tid + j * 256;
        int r = i >> 2, b16 = (i & 3) * 16;
        *(uint4*)(stage + A_H + r * ASTR2 + b16) = p.a[j];
    }
#pragma unroll
    for (int j = 0; j < 2; ++j) {
        int i = tid + j * 256;
        int r = i >> 2, b16 = (i & 3) * 16;
        *(uint4*)(stage + B_HI + r * ASTR2 + b16) = p.bh[j];
        *(uint4*)(stage + B_LO + r * ASTR2 + b16) = p.bl[j];
    }
}

__global__ __launch_bounds__(256)
void gemm_mma_kernel(const float* __restrict__ bias, int layer) {
    extern __shared__ char smem[];
    const int F  = layer ? F1 : F0;
    const int nc = F / 32;
    const int T  = 2 * nc;
    const int row0 = blockIdx.x * 128;
    const int col0 = blockIdx.y * 128;
    __half* C = layer ? g_zh : g_h1h;

    const int tid = threadIdx.x, wid = tid >> 5, lane = tid & 31;
    const int wm0 = (wid >> 2) * 64;
    const int wn0 = (wid & 3) * 32;

    float acc[4][4][4];
#pragma unroll
    for (int a = 0; a < 4; ++a)
#pragma unroll
        for (int b = 0; b < 4; ++b)
#pragma unroll
            for (int c = 0; c < 4; ++c) acc[a][b][c] = 0.f;

    Pref p;
    ldg_chunk(p, layer, F, nc, 0, row0, col0);
    sts_chunk(p, smem);
    __syncthreads();

    const uint32_t sbase = smem_u32(smem);
    const int b_row = ((lane >> 4) & 1) * 8 + (lane & 7);
    const int b_khalf = ((lane >> 3) & 1) * 8;
    const int a_row = lane & 15;
    const int a_khalf = ((lane >> 4) & 1) * 8;

    for (int t = 0; t < T; ++t) {
        if (t + 1 < T) ldg_chunk(p, layer, F, nc, t + 1, row0, col0);
        const uint32_t sb = sbase + (uint32_t)(t & 1) * STAGE_BYTES;
#pragma unroll
        for (int ks = 0; ks < 2; ++ks) {
            uint32_t bhi[4][2], blo[4][2];
            {
                uint32_t r[4];
                uint32_t ad = sb + B_HI + (uint32_t)((wn0 + b_row) * ASTR2 + (ks * 16 + b_khalf) * 2);
                ldmx4(r, ad);
                bhi[0][0] = r[0]; bhi[0][1] = r[1]; bhi[1][0] = r[2]; bhi[1][1] = r[3];
                ldmx4(r, ad + 16 * ASTR2);
                bhi[2][0] = r[0]; bhi[2][1] = r[1]; bhi[3][0] = r[2]; bhi[3][1] = r[3];
                uint32_t ad2 = sb + B_LO + (uint32_t)((wn0 + b_row) * ASTR2 + (ks * 16 + b_khalf) * 2);
                ldmx4(r, ad2);
                blo[0][0] = r[0]; blo[0][1] = r[1]; blo[1][0] = r[2]; blo[1][1] = r[3];
                ldmx4(r, ad2 + 16 * ASTR2);
                blo[2][0] = r[0]; blo[2][1] = r[1]; blo[3][0] = r[2]; blo[3][1] = r[3];
            }
            uint32_t ah[4][4];
#pragma unroll
            for (int mt = 0; mt < 4; ++mt) {
                uint32_t roff = (uint32_t)((wm0 + mt * 16 + a_row) * ASTR2 + (ks * 16 + a_khalf) * 2);
                ldmx4(ah[mt], sb + A_H + roff);
            }
#pragma unroll
            for (int mt = 0; mt < 4; ++mt)
#pragma unroll
                for (int nt = 0; nt < 4; ++nt) {
                    hmma(acc[mt][nt], ah[mt], bhi[nt]);
                    hmma(acc[mt][nt], ah[mt], blo[nt]);
                }
        }
        if (t + 1 < T) sts_chunk(p, smem + ((t + 1) & 1) * STAGE_BYTES);
        __syncthreads();
    }

    // epilogue: bias + relu + fp16 store
#pragma unroll
    for (int mt = 0; mt < 4; ++mt) {
        int rbase = row0 + wm0 + mt * 16 + (lane >> 2);
#pragma unroll
        for (int hh = 0; hh < 2; ++hh) {
            int gm = rbase + hh * 8;
            if (gm < N_NODES) {
                __half* crow = C + (size_t)gm * HID;
#pragma unroll
                for (int nt = 0; nt < 4; ++nt) {
                    int cn = col0 + wn0 + nt * 8 + (lane & 3) * 2;
                    float v0 = acc[mt][nt][hh * 2]     + bias[cn];
                    float v1 = acc[mt][nt][hh * 2 + 1] + bias[cn + 1];
                    *(__half2*)(crow + cn) = __floats2half2_rn(fmaxf(v0, 0.f), fmaxf(v1, 0.f));
                }
            }
        }
    }
}

// ---------------- pair scoring: sigmoid(dot(z[src], z[dst])), fp16 gather ----------------
__global__ void pair_kernel(const int* __restrict__ src,
                            const int* __restrict__ dst,
                            float* __restrict__ out) {
    int gw = (blockIdx.x * blockDim.x + threadIdx.x) >> 5;
    int lane = threadIdx.x & 31;
    if (gw >= N_PAIRS) return;
    int a = src[gw], b = dst[gw];
    uint4 va = ((const uint4*)(g_zh + (size_t)a * HID))[lane];
    uint4 vb = ((const uint4*)(g_zh + (size_t)b * HID))[lane];
    const __half2* ha = (const __half2*)&va;
    const __half2* hb = (const __half2*)&vb;
    float acc = 0.f;
#pragma unroll
    for (int i = 0; i < 4; ++i) {
        float2 fa = __half22float2(ha[i]);
        float2 fb = __half22float2(hb[i]);
        acc += fa.x * fb.x + fa.y * fb.y;
    }
#pragma unroll
    for (int o = 16; o; o >>= 1) acc += __shfl_xor_sync(0xFFFFFFFFu, acc, o);
    if (lane == 0) out[gw] = 1.f / (1.f + expf(-acc));
}

// ---------------- launch ----------------
extern "C" void kernel_launch(void* const* d_in, const int* in_sizes, int n_in,
                              void* d_out, int out_size) {
    const float* x           = (const float*)d_in[0];
    const int*   tok_ids     = (const int*)  d_in[1];
    const float* scores      = (const float*)d_in[2];
    const int*   cat_ids     = (const int*)  d_in[3];
    const int*   edge_index  = (const int*)  d_in[4];
    const int*   src         = (const int*)  d_in[5];
    const int*   dst         = (const int*)  d_in[6];
    const float* trait_embed = (const float*)d_in[7];
    const float* cat_embed   = (const float*)d_in[8];
    const float* proj_W      = (const float*)d_in[9];
    const float* proj_b      = (const float*)d_in[10];
    const float* W_l0        = (const float*)d_in[11];
    const float* b_l0        = (const float*)d_in[12];
    const float* W_r0        = (const float*)d_in[13];
    const float* W_l1        = (const float*)d_in[14];
    const float* b_l1        = (const float*)d_in[15];
    const float* W_r1        = (const float*)d_in[16];
    float* out = (float*)d_out;

    const int* e_src = edge_index;
    const int* e_dst = edge_index + N_EDGES;

    cudaFuncSetAttribute(gemm_mma_kernel,
                         cudaFuncAttributeMaxDynamicSharedMemorySize, SMEM_GEMM_TOTAL);

    gwas_kernel<<<(N_NODES + 7) / 8, 256>>>(x, tok_ids, scores, cat_ids,
                                            trait_embed, cat_embed, proj_W, proj_b);

    wsplit_all_kernel<<<(256 * 256 + 255) / 256, 256>>>(W_l0, W_r0, W_l1, W_r1);

    zero_cnt_kernel<<<(N_NODES + 255) / 256, 256>>>();
    count_kernel<<<(N_EDGES + 255) / 256, 256>>>(e_dst);
    scan1_kernel<<<SCAN_GRID, SCAN_BLK>>>();
    scan2_kernel<<<1, SCAN_BLK>>>();
    scan3_kernel<<<SCAN_GRID, SCAN_BLK>>>();
    fill_kernel<<<(N_EDGES + 255) / 256, 256>>>(e_src, e_dst);

    const dim3 ggrid((N_NODES + 127) / 128, 2);

    // Layer 0
    {
        dim3 blk(F0 / 8, 12);   // 20 x 12 = 240
        aggregate_kernel<<<(N_NODES + 11) / 12, blk>>>(0);
        gemm_mma_kernel<<<ggrid, 256, SMEM_GEMM_TOTAL>>>(b_l0, 0);
    }
    // Layer 1
    {
        dim3 blk(F1 / 8, 8);    // 32 x 8 = 256
        aggregate_kernel<<<(N_NODES + 7) / 8, blk>>>(1);
        gemm_mma_kernel<<<ggrid, 256, SMEM_GEMM_TOTAL>>>(b_l1, 1);
    }

    pair_kernel<<<(N_PAIRS * 32 + 255) / 256, 256>>>(src, dst, out);
}

// round 6
// speedup vs baseline: 5.8628x; 1.2254x over previous
#include <cuda_runtime.h>
#include <cuda_fp16.h>
#include <math.h>
#include <stdint.h>

#define N_NODES 50000
#define N_EDGES 800000
#define N_PAIRS 100000
#define IN_CH 128
#define HID 256
#define EMB 32
#define CAT_EMB 8
#define MAX_TOK 20
#define F0 160   // IN_CH + EMB
#define F1 256   // HID

// ---------------- scratch (fp16 feature tables, fp32 accumulation) ----------------
__device__ __half g_h0h[N_NODES * F0];
__device__ __half g_aggh[N_NODES * F1];
__device__ __half g_h1h[N_NODES * F1];
__device__ __half g_zh[N_NODES * F1];
__device__ int    g_cnt[N_NODES];
__device__ int    g_off[N_NODES + 1];
__device__ int    g_cur[N_NODES];
__device__ int    g_csr[N_EDGES];
__device__ float  g_invdeg[N_NODES];

// pre-transposed fp16 weights: slot = layer*2 + (0:W_l, 1:W_r); layout [n][k]
__device__ __half g_wt[4][256 * 256];

#define SCAN_BLK 256
#define SCAN_GRID ((N_NODES + SCAN_BLK - 1) / SCAN_BLK)
__device__ int g_bsum[SCAN_GRID];

// ================= mma.sync helpers =================
__device__ __forceinline__ uint32_t smem_u32(const void* p) {
    uint32_t a;
    asm("{ .reg .u64 t; cvta.to.shared.u64 t, %1; cvt.u32.u64 %0, t; }" : "=r"(a) : "l"(p));
    return a;
}
__device__ __forceinline__ void ldmx4(uint32_t* r, uint32_t addr) {
    asm volatile("ldmatrix.sync.aligned.m8n8.x4.shared.b16 {%0,%1,%2,%3}, [%4];"
                 : "=r"(r[0]), "=r"(r[1]), "=r"(r[2]), "=r"(r[3]) : "r"(addr));
}
__device__ __forceinline__ void hmma(float* c, const uint32_t* a, const uint32_t* b) {
    asm volatile("mma.sync.aligned.m16n8k16.row.col.f32.f16.f16.f32 "
                 "{%0,%1,%2,%3}, {%4,%5,%6,%7}, {%8,%9}, {%0,%1,%2,%3};"
                 : "+f"(c[0]), "+f"(c[1]), "+f"(c[2]), "+f"(c[3])
                 : "r"(a[0]), "r"(a[1]), "r"(a[2]), "r"(a[3]), "r"(b[0]), "r"(b[1]));
}

// smem stage layout (fp16, row stride 40 elems = 80B -> conflict-free ldmatrix)
#define ASTR2 80        // row stride in bytes
#define A_H  0
#define B_H  10240
#define STAGE_BYTES 20480
#define SMEM_GEMM_TOTAL (2 * STAGE_BYTES)   // 40 KB

// ---------------- GWAS encoder + concat into h0 (fp16); also zeroes g_cnt ----------------
__global__ void gwas_kernel(const float* __restrict__ x,
                            const int* __restrict__ tok,
                            const float* __restrict__ scores,
                            const int* __restrict__ cat,
                            const float* __restrict__ trait_embed,
                            const float* __restrict__ cat_embed,
                            const float* __restrict__ proj_W,
                            const float* __restrict__ proj_b) {
    // fold zero_cnt into this kernel (runs before count_kernel)
    int gt = blockIdx.x * blockDim.x + threadIdx.x;
    if (gt < N_NODES) g_cnt[gt] = 0;

    int warp_in_block = threadIdx.x >> 5;
    int lane = threadIdx.x & 31;
    int n = blockIdx.x * (blockDim.x >> 5) + warp_in_block;
    if (n >= N_NODES) return;

    __shared__ float sh_acc[8][41];
    float acc_trait = 0.f, acc_cat = 0.f, acc_s = 0.f, wsum = 0.f;

    const int*   tk = tok    + (long long)n * MAX_TOK;
    const float* sc = scores + (long long)n * MAX_TOK;
    const int*   ct = cat    + (long long)n * MAX_TOK;

    for (int t = 0; t < MAX_TOK; ++t) {
        int   tid = tk[t];
        float s   = sc[t];
        int   cid = ct[t];
        float w   = (tid != 0) ? s : 0.f;
        wsum += w;
        acc_trait += w * trait_embed[tid * EMB + lane];
        if (lane < CAT_EMB) acc_cat += w * cat_embed[cid * CAT_EMB + lane];
        acc_s += w * s;
    }
    sh_acc[warp_in_block][lane] = acc_trait;
    if (lane < CAT_EMB) sh_acc[warp_in_block][EMB + lane] = acc_cat;
    if (lane == 0)      sh_acc[warp_in_block][EMB + CAT_EMB] = acc_s;
    __syncwarp();

    float inv = 1.f / fmaxf(wsum, 1e-8f);
    float o = wsum * proj_b[lane];
    const float* shv = sh_acc[warp_in_block];
#pragma unroll
    for (int k = 0; k < 41; ++k)
        o += shv[k] * proj_W[k * EMB + lane];

    __half* hrow = g_h0h + (long long)n * F0;
    hrow[IN_CH + lane] = __float2half_rn(o * inv);
    const float* xrow = x + (long long)n * IN_CH;
#pragma unroll
    for (int i = 0; i < 4; ++i)
        hrow[lane + i * 32] = __float2half_rn(xrow[lane + i * 32]);
}

// ---------------- weight transpose -> fp16 (all 4 slots, one kernel) ----------------
__global__ void wsplit_all_kernel(const float* __restrict__ Wl0, const float* __restrict__ Wr0,
                                  const float* __restrict__ Wl1, const float* __restrict__ Wr1) {
    int idx = blockIdx.x * blockDim.x + threadIdx.x;
    if (idx >= 256 * 256) return;
    int n = idx & 255, j = idx >> 8;   // j = k index
    const float* Ws[4] = {Wl0, Wr0, Wl1, Wr1};
    const int    Ks[4] = {F0, F0, F1, F1};
#pragma unroll
    for (int slot = 0; slot < 4; ++slot) {
        int K = Ks[slot];
        if (j < K)
            g_wt[slot][n * K + j] = __float2half_rn(Ws[slot][j * 256 + n]);
    }
}

// ---------------- CSR build ----------------
__global__ void count_kernel(const int* __restrict__ e_dst) {
    int e = blockIdx.x * blockDim.x + threadIdx.x;
    if (e < N_EDGES) atomicAdd(&g_cnt[e_dst[e]], 1);
}
__global__ void scan1_kernel() {
    __shared__ int sh[SCAN_BLK];
    int tid = threadIdx.x;
    int i = blockIdx.x * SCAN_BLK + tid;
    int v = (i < N_NODES) ? g_cnt[i] : 0;
    sh[tid] = v;
    __syncthreads();
#pragma unroll
    for (int off = 1; off < SCAN_BLK; off <<= 1) {
        int t = (tid >= off) ? sh[tid - off] : 0;
        __syncthreads();
        sh[tid] += t;
        __syncthreads();
    }
    if (i < N_NODES) g_off[i] = sh[tid] - v;
    if (tid == SCAN_BLK - 1) g_bsum[blockIdx.x] = sh[tid];
}
__global__ void scan2_kernel() {
    __shared__ int sh[SCAN_BLK];
    int tid = threadIdx.x;
    int v = (tid < SCAN_GRID) ? g_bsum[tid] : 0;
    sh[tid] = v;
    __syncthreads();
#pragma unroll
    for (int off = 1; off < SCAN_BLK; off <<= 1) {
        int t = (tid >= off) ? sh[tid - off] : 0;
        __syncthreads();
        sh[tid] += t;
        __syncthreads();
    }
    if (tid < SCAN_GRID) g_bsum[tid] = sh[tid] - v;
    if (tid == 0) g_off[N_NODES] = N_EDGES;
}
__global__ void scan3_kernel() {
    int tid = threadIdx.x;
    int i = blockIdx.x * SCAN_BLK + tid;
    if (i < N_NODES) {
        int o = g_off[i] + g_bsum[blockIdx.x];
        g_off[i] = o;
        g_cur[i] = o;
        g_invdeg[i] = 1.0f / fmaxf((float)g_cnt[i], 1.0f);
    }
}
__global__ void fill_kernel(const int* __restrict__ e_src, const int* __restrict__ e_dst) {
    int e = blockIdx.x * blockDim.x + threadIdx.x;
    if (e < N_EDGES) {
        int d = e_dst[e];
        int pos = atomicAdd(&g_cur[d], 1);
        g_csr[pos] = e_src[e];
    }
}

// ---------------- mean aggregation (fp16 gather, fp32 accum, fp16 store) ----------------
__global__ void aggregate_kernel(int layer) {
    const uint4* feat = (const uint4*)(layer ? g_h1h : g_h0h);
    int Fv8 = (layer ? F1 : F0) >> 3;
    int n = blockIdx.x * blockDim.y + threadIdx.y;
    if (n >= N_NODES) return;
    int c = threadIdx.x;
    int s = g_off[n], e = g_off[n + 1];
    float acc[8];
#pragma unroll
    for (int i = 0; i < 8; ++i) acc[i] = 0.f;
    for (int j = s; j < e; ++j) {
        int srcn = g_csr[j];
        uint4 v = feat[(size_t)srcn * Fv8 + c];
        const __half2* hv = (const __half2*)&v;
#pragma unroll
        for (int i = 0; i < 4; ++i) {
            float2 f = __half22float2(hv[i]);
            acc[2 * i]     += f.x;
            acc[2 * i + 1] += f.y;
        }
    }
    float sc = g_invdeg[n];
    uint4 outv;
    __half2* ho = (__half2*)&outv;
#pragma unroll
    for (int i = 0; i < 4; ++i)
        ho[i] = __floats2half2_rn(acc[2 * i] * sc, acc[2 * i + 1] * sc);
    ((uint4*)g_aggh)[(size_t)n * Fv8 + c] = outv;
}

// ---------------- tensor-core GEMM: C = relu(agg@Wl + x@Wr + b), fp16 ----------------
struct Pref {
    uint4 a[2], b[2];
};

__device__ __forceinline__ void ldg_chunk(Pref& p, int layer, int F, int nc,
                                          int t, int row0, int col0) {
    int hf = (t >= nc) ? 1 : 0;
    int k0 = (t - hf * nc) * 32;
    const __half* Asrc = hf ? (layer ? g_h1h : g_h0h) : g_aggh;
    const __half* Bsrc = g_wt[layer * 2 + hf];
    int tid = threadIdx.x;
#pragma unroll
    for (int j = 0; j < 2; ++j) {
        int i = tid + j * 256;
        int r = i >> 2, q8 = (i & 3) * 8;
        int gm = row0 + r;
        p.a[j] = (gm < N_NODES) ? *(const uint4*)(Asrc + (size_t)gm * F + k0 + q8)
                                : make_uint4(0, 0, 0, 0);
        p.b[j] = *(const uint4*)(Bsrc + (size_t)(col0 + r) * F + k0 + q8);
    }
}

__device__ __forceinline__ void sts_chunk(const Pref& p, char* stage) {
    int tid = threadIdx.x;
#pragma unroll
    for (int j = 0; j < 2; ++j) {
        int i = tid + j * 256;
        int r = i >> 2, b16 = (i & 3) * 16;
        *(uint4*)(stage + A_H + r * ASTR2 + b16) = p.a[j];
        *(uint4*)(stage + B_H + r * ASTR2 + b16) = p.b[j];
    }
}

__global__ __launch_bounds__(256)
void gemm_mma_kernel(const float* __restrict__ bias, int layer) {
    extern __shared__ char smem[];
    const int F  = layer ? F1 : F0;
    const int nc = F / 32;
    const int T  = 2 * nc;
    const int row0 = blockIdx.x * 128;
    const int col0 = blockIdx.y * 128;
    __half* C = layer ? g_zh : g_h1h;

    const int tid = threadIdx.x, wid = tid >> 5, lane = tid & 31;
    const int wm0 = (wid >> 2) * 64;
    const int wn0 = (wid & 3) * 32;

    float acc[4][4][4];
#pragma unroll
    for (int a = 0; a < 4; ++a)
#pragma unroll
        for (int b = 0; b < 4; ++b)
#pragma unroll
            for (int c = 0; c < 4; ++c) acc[a][b][c] = 0.f;

    Pref p;
    ldg_chunk(p, layer, F, nc, 0, row0, col0);
    sts_chunk(p, smem);
    __syncthreads();

    const uint32_t sbase = smem_u32(smem);
    const int b_row = ((lane >> 4) & 1) * 8 + (lane & 7);
    const int b_khalf = ((lane >> 3) & 1) * 8;
    const int a_row = lane & 15;
    const int a_khalf = ((lane >> 4) & 1) * 8;

    for (int t = 0; t < T; ++t) {
        if (t + 1 < T) ldg_chunk(p, layer, F, nc, t + 1, row0, col0);
        const uint32_t sb = sbase + (uint32_t)(t & 1) * STAGE_BYTES;
#pragma unroll
        for (int ks = 0; ks < 2; ++ks) {
            uint32_t bh[4][2];
            {
                uint32_t r[4];
                uint32_t ad = sb + B_H + (uint32_t)((wn0 + b_row) * ASTR2 + (ks * 16 + b_khalf) * 2);
                ldmx4(r, ad);
                bh[0][0] = r[0]; bh[0][1] = r[1]; bh[1][0] = r[2]; bh[1][1] = r[3];
                ldmx4(r, ad + 16 * ASTR2);
                bh[2][0] = r[0]; bh[2][1] = r[1]; bh[3][0] = r[2]; bh[3][1] = r[3];
            }
            uint32_t ah[4][4];
#pragma unroll
            for (int mt = 0; mt < 4; ++mt) {
                uint32_t roff = (uint32_t)((wm0 + mt * 16 + a_row) * ASTR2 + (ks * 16 + a_khalf) * 2);
                ldmx4(ah[mt], sb + A_H + roff);
            }
#pragma unroll
            for (int mt = 0; mt < 4; ++mt)
#pragma unroll
                for (int nt = 0; nt < 4; ++nt)
                    hmma(acc[mt][nt], ah[mt], bh[nt]);
        }
        if (t + 1 < T) sts_chunk(p, smem + ((t + 1) & 1) * STAGE_BYTES);
        __syncthreads();
    }

    // epilogue: bias + relu + fp16 store
#pragma unroll
    for (int mt = 0; mt < 4; ++mt) {
        int rbase = row0 + wm0 + mt * 16 + (lane >> 2);
#pragma unroll
        for (int hh = 0; hh < 2; ++hh) {
            int gm = rbase + hh * 8;
            if (gm < N_NODES) {
                __half* crow = C + (size_t)gm * HID;
#pragma unroll
                for (int nt = 0; nt < 4; ++nt) {
                    int cn = col0 + wn0 + nt * 8 + (lane & 3) * 2;
                    float v0 = acc[mt][nt][hh * 2]     + bias[cn];
                    float v1 = acc[mt][nt][hh * 2 + 1] + bias[cn + 1];
                    *(__half2*)(crow + cn) = __floats2half2_rn(fmaxf(v0, 0.f), fmaxf(v1, 0.f));
                }
            }
        }
    }
}

// ---------------- pair scoring: sigmoid(dot(z[src], z[dst])), fp16 gather ----------------
__global__ void pair_kernel(const int* __restrict__ src,
                            const int* __restrict__ dst,
                            float* __restrict__ out) {
    int gw = (blockIdx.x * blockDim.x + threadIdx.x) >> 5;
    int lane = threadIdx.x & 31;
    if (gw >= N_PAIRS) return;
    int a = src[gw], b = dst[gw];
    uint4 va = ((const uint4*)(g_zh + (size_t)a * HID))[lane];
    uint4 vb = ((const uint4*)(g_zh + (size_t)b * HID))[lane];
    const __half2* ha = (const __half2*)&va;
    const __half2* hb = (const __half2*)&vb;
    float acc = 0.f;
#pragma unroll
    for (int i = 0; i < 4; ++i) {
        float2 fa = __half22float2(ha[i]);
        float2 fb = __half22float2(hb[i]);
        acc += fa.x * fb.x + fa.y * fb.y;
    }
#pragma unroll
    for (int o = 16; o; o >>= 1) acc += __shfl_xor_sync(0xFFFFFFFFu, acc, o);
    if (lane == 0) out[gw] = 1.f / (1.f + expf(-acc));
}

// ---------------- launch ----------------
extern "C" void kernel_launch(void* const* d_in, const int* in_sizes, int n_in,
                              void* d_out, int out_size) {
    const float* x           = (const float*)d_in[0];
    const int*   tok_ids     = (const int*)  d_in[1];
    const float* scores      = (const float*)d_in[2];
    const int*   cat_ids     = (const int*)  d_in[3];
    const int*   edge_index  = (const int*)  d_in[4];
    const int*   src         = (const int*)  d_in[5];
    const int*   dst         = (const int*)  d_in[6];
    const float* trait_embed = (const float*)d_in[7];
    const float* cat_embed   = (const float*)d_in[8];
    const float* proj_W      = (const float*)d_in[9];
    const float* proj_b      = (const float*)d_in[10];
    const float* W_l0        = (const float*)d_in[11];
    const float* b_l0        = (const float*)d_in[12];
    const float* W_r0        = (const float*)d_in[13];
    const float* W_l1        = (const float*)d_in[14];
    const float* b_l1        = (const float*)d_in[15];
    const float* W_r1        = (const float*)d_in[16];
    float* out = (float*)d_out;

    const int* e_src = edge_index;
    const int* e_dst = edge_index + N_EDGES;

    cudaFuncSetAttribute(gemm_mma_kernel,
                         cudaFuncAttributeMaxDynamicSharedMemorySize, SMEM_GEMM_TOTAL);

    gwas_kernel<<<(N_NODES + 7) / 8, 256>>>(x, tok_ids, scores, cat_ids,
                                            trait_embed, cat_embed, proj_W, proj_b);

    wsplit_all_kernel<<<(256 * 256 + 255) / 256, 256>>>(W_l0, W_r0, W_l1, W_r1);

    count_kernel<<<(N_EDGES + 255) / 256, 256>>>(e_dst);
    scan1_kernel<<<SCAN_GRID, SCAN_BLK>>>();
    scan2_kernel<<<1, SCAN_BLK>>>();
    scan3_kernel<<<SCAN_GRID, SCAN_BLK>>>();
    fill_kernel<<<(N_EDGES + 255) / 256, 256>>>(e_src, e_dst);

    const dim3 ggrid((N_NODES + 127) / 128, 2);

    // Layer 0
    {
        dim3 blk(F0 / 8, 12);   // 20 x 12 = 240
        aggregate_kernel<<<(N_NODES + 11) / 12, blk>>>(0);
        gemm_mma_kernel<<<ggrid, 256, SMEM_GEMM_TOTAL>>>(b_l0, 0);
    }
    // Layer 1
    {
        dim3 blk(F1 / 8, 8);    // 32 x 8 = 256
        aggregate_kernel<<<(N_NODES + 7) / 8, blk>>>(1);
        gemm_mma_kernel<<<ggrid, 256, SMEM_GEMM_TOTAL>>>(b_l1, 1);
    }

    pair_kernel<<<(N_PAIRS * 32 + 255) / 256, 256>>>(src, dst, out);
}